// round 5
// baseline (speedup 1.0000x reference)
#include <cuda_runtime.h>

#define S 64
#define MAXT 262144
#define L 512
#define NCMAX ((MAXT + L - 1) / L)

// ---- scratch (__device__ globals: no allocation allowed) ----
__device__ float g_e_buf[(size_t)MAXT * S];                    // e_t rows (+pad row)
__device__ int g_rollpad[MAXT + 96];                           // rolls padded with last value
__device__ unsigned char g_walk[(size_t)NCMAX * S * L];        // per-chunk walks (16 MB)
__device__ int g_boundary[NCMAX + 2];
__device__ int g_final_state;
__device__ float g_final_score;

__device__ __forceinline__ float fmax3(float a, float b, float c) {
    return fmaxf(fmaxf(a, b), c);
}

// Packed f32x2 add (Blackwell): two independent IEEE-rn f32 adds -> bit-exact.
#define ADDX2(out, a, b) \
    asm("add.rn.f32x2 %0, %1, %2;" : "=l"(out) : "l"(a), "l"(b))
#define UNPACKX2(lo, hi, in) \
    asm("mov.b64 {%0, %1}, %2;" : "=r"(lo), "=r"(hi) : "l"(in))
#define PACKX2(out, lo, hi) \
    asm("mov.b64 %0, {%1, %2};" : "=l"(out) : "r"(lo), "r"(hi))

// =====================================================================
// Kernel 0a: pad rolls so the serial loop needs no clamping
// =====================================================================
__global__ void prep_kernel(const int* __restrict__ rolls, int T)
{
    int i = blockIdx.x * blockDim.x + threadIdx.x;
    if (i < T + 96) g_rollpad[i] = rolls[(i < T) ? i : (T - 1)];
}

// Kernel 0b: no-op launch-index shims (keep ncu -s 5 landing on fwd_kernel)
__global__ void dummy_kernel() {}

// =====================================================================
// Kernel 1: serial Viterbi forward (values only), 64 threads = 2 warps.
// Thread j owns state j: all 64 candidates, no shfl, single bar/step.
// =====================================================================
__global__ __launch_bounds__(64, 1)
void fwd_kernel(const int* __restrict__ rolls,
                const float* __restrict__ trans,
                const float* __restrict__ table, int T)
{
    __shared__ __align__(16) float smem_e[2][S];   // double-buffered e row
    __shared__ float smem_d[S];

    const int j = threadIdx.x;                      // state 0..63

    // TR row packed as 32 f32x2 pairs (one-time cost)
    unsigned long long trp[32];
    {
#pragma unroll
        for (int k = 0; k < 32; k++) {
            unsigned int lo = __float_as_uint(trans[j * 65 + 2 * k]);
            unsigned int hi = __float_as_uint(trans[j * 65 + 2 * k + 1]);
            PACKX2(trp[k], lo, hi);
        }
    }

    // ---- init: delta_0 = trans[:,64] + ll_0 ; e_1 = ll_1 + delta_0 ----
    {
        int r0 = rolls[0];
        int r1 = rolls[(T > 1) ? 1 : 0];
        float ll0 = table[r0 * S + j];
        float d0 = trans[j * 65 + 64] + ll0;
        if (T == 1) smem_d[j] = d0;
        float ll1 = table[r1 * S + j];
        float e1 = ll1 + d0;
        smem_e[1][j] = e1;
        g_e_buf[j] = e1;
    }
    // ll ring: llCur = ll_{t+1} at loop entry (t=1 -> ll_2), llNxt = ll_3
    float llCur = table[rolls[(T > 2) ? 2 : (T - 1)] * S + j];
    float llNxt = table[rolls[(T > 3) ? 3 : (T - 1)] * S + j];
    __syncthreads();

    float delta = 0.0f;

    // One Viterbi step, STATIC read/write parity RP/WP.
    // E via LDS.128 (broadcast), candidates via packed add.rn.f32x2
    // (bit-exact), 63-FMNMX selection tree (shape-free), no shfl.
#define VSTEP(RP, WP, tcur)                                                    \
    {                                                                          \
        int rn = g_rollpad[(tcur) + 3];                                        \
        float llN = table[rn * S + j];                                         \
        float mq[16];                                                          \
        {                                                                      \
            const ulonglong2* eb =                                             \
                reinterpret_cast<const ulonglong2*>(smem_e[RP]);               \
            _Pragma("unroll")                                                  \
            for (int q = 0; q < 16; q++) {                                     \
                ulonglong2 ev = eb[q];                                         \
                unsigned long long s0, s1;                                     \
                ADDX2(s0, ev.x, trp[2 * q]);                                   \
                ADDX2(s1, ev.y, trp[2 * q + 1]);                               \
                unsigned int u0, u1, u2, u3;                                   \
                UNPACKX2(u0, u1, s0);                                          \
                UNPACKX2(u2, u3, s1);                                          \
                float a = __uint_as_float(u0), b = __uint_as_float(u1);        \
                float c = __uint_as_float(u2), d = __uint_as_float(u3);        \
                mq[q] = fmaxf(fmaxf(a, b), fmaxf(c, d));                       \
            }                                                                  \
        }                                                                      \
        float a0 = fmax3(mq[0], mq[1], mq[2]);                                 \
        float a1 = fmax3(mq[3], mq[4], mq[5]);                                 \
        float a2 = fmax3(mq[6], mq[7], mq[8]);                                 \
        float a3 = fmax3(mq[9], mq[10], mq[11]);                               \
        float a4 = fmax3(mq[12], mq[13], mq[14]);                              \
        float b0 = fmax3(a0, a1, a2);                                          \
        float b1 = fmax3(a3, a4, mq[15]);                                      \
        delta = fmaxf(b0, b1);                                                 \
        float ep = llCur + delta;        /* e_{t+1} = ll_{t+1} + delta_t */    \
        smem_e[WP][j] = ep;                                                    \
        g_e_buf[(size_t)(tcur) * S + j] = ep;   /* padded row: no guard */     \
        __syncthreads();                                                       \
        llCur = llNxt; llNxt = llN;                                            \
    }

    int t = 1;
    for (; t + 1 < T; t += 2) {        // t odd: read[1]->write[0]; then read[0]->write[1]
        VSTEP(1, 0, t);
        VSTEP(0, 1, t + 1);
    }
    if (t < T) {
        VSTEP(1, 0, t);
    }
#undef VSTEP

    if (T > 1) smem_d[j] = delta;
    __syncthreads();
    if (j == 0) {
        float best = smem_d[0]; int bi = 0;
        for (int q = 1; q < S; q++) {           // first-argmax (strict >)
            float vq = smem_d[q];
            if (vq > best) { best = vq; bi = q; }
        }
        g_final_state = bi;
        g_final_score = best;
    }
}

// =====================================================================
// Kernel 2: per-chunk backpointer recompute (bit-identical candidates,
// first-argmax via ascending strict >) + all-64-endstate backtrack walks.
// Chunk c covers bp steps t in (c*L, (c+1)*L] ∩ [1, T-1].
// =====================================================================
__global__ __launch_bounds__(512, 1)
void bp_chunk_kernel(const float* __restrict__ trans, int T)
{
    __shared__ signed char bp_s[L * S];                 // 32 KB
    __shared__ __align__(16) float se[8][S];
    const int c = blockIdx.x;
    const int tid = threadIdx.x;
    const int tg = tid >> 6;                            // 0..7 row subgroup
    const int j = tid & 63;
    int nr = (T - 1) - c * L; if (nr > L) nr = L; if (nr < 0) nr = 0;

    float TRv[64];
#pragma unroll
    for (int i = 0; i < 64; i++) TRv[i] = trans[j * 65 + i];

    for (int k = 0; k < L / 8; k++) {
        const int r = k * 8 + tg;
        const bool act = r < nr;
        if (act) se[tg][j] = g_e_buf[((size_t)(c * L + r)) * S + j];
        __syncthreads();
        if (act) {
            const float4* ep = reinterpret_cast<const float4*>(se[tg]);
            float4 e0 = ep[0];
            float m = TRv[0] + e0.x; int a = 0;
            float cc = TRv[1] + e0.y; if (cc > m) { m = cc; a = 1; }
            cc = TRv[2] + e0.z; if (cc > m) { m = cc; a = 2; }
            cc = TRv[3] + e0.w; if (cc > m) { m = cc; a = 3; }
#pragma unroll
            for (int q = 1; q < 16; q++) {
                float4 ev = ep[q];
                cc = TRv[4*q]   + ev.x; if (cc > m) { m = cc; a = 4*q;   }
                cc = TRv[4*q+1] + ev.y; if (cc > m) { m = cc; a = 4*q+1; }
                cc = TRv[4*q+2] + ev.z; if (cc > m) { m = cc; a = 4*q+2; }
                cc = TRv[4*q+3] + ev.w; if (cc > m) { m = cc; a = 4*q+3; }
            }
            bp_s[r * S + j] = (signed char)a;
        }
        __syncthreads();
    }

    // walk all 64 hypothetical end states back through the chunk
    if (tid < S) {
        int s = tid;
        const size_t wb = ((size_t)c * S + tid) * L;
        if (nr < L) g_walk[wb + nr] = (unsigned char)s;  // last chunk: self at T-1
        for (int r = nr - 1; r >= 0; r--) {
            s = bp_s[r * S + s];                          // state at time c*L + r
            g_walk[wb + r] = (unsigned char)s;
        }
    }
}

// =====================================================================
// Kernel 3: serial chunk-map composition -> per-chunk boundary states
// =====================================================================
__global__ void compose_kernel(int T)
{
    __shared__ unsigned char mp[L * S];
    int nc = (T >= 2) ? ((T - 2) / L + 1) : 1;
    for (int q = threadIdx.x; q < nc * S; q += blockDim.x)
        mp[q] = g_walk[(size_t)q * L];
    __syncthreads();
    if (threadIdx.x == 0) {
        int s = g_final_state;
        g_boundary[nc] = s;
        for (int c = nc - 1; c >= 0; c--) {
            s = mp[c * S + s];
            g_boundary[c] = s;
        }
    }
}

// =====================================================================
// Kernel 4: parallel path fill, reverse-time order: out[T-1-t] = s_t
// =====================================================================
__global__ void fill_kernel(float* __restrict__ out, int T, int out_size)
{
    const int c = blockIdx.x;
    const int m = threadIdx.x;
    const int t = c * L + m;
    if (t < T) {
        const int sel = g_boundary[c + 1];
        unsigned char s = g_walk[((size_t)c * S + sel) * L + m];
        const int oi = T - 1 - t;
        if (oi >= 0 && oi < out_size) out[oi] = (float)s;
    }
    if (c == 0 && m == 0 && T < out_size) out[T] = g_final_score;
}

// =====================================================================
extern "C" void kernel_launch(void* const* d_in, const int* in_sizes, int n_in,
                              void* d_out, int out_size)
{
    const int* rolls = nullptr;
    const float* trans = nullptr;
    const float* table = nullptr;
    int T = 0;
    for (int i = 0; i < n_in; i++) {
        const int sz = in_sizes[i];
        if (sz == 64 * 65)       trans = (const float*)d_in[i];
        else if (sz == 128 * 64) table = (const float*)d_in[i];
        else { rolls = (const int*)d_in[i]; T = sz; }
    }
    if (!rolls || !trans || !table || T < 1) return;
    if (T > MAXT) T = MAXT;

    int nc = (T >= 2) ? ((T - 2) / L + 1) : 1;

    // 3 cheap launches ahead of fwd so ncu's fixed "-s 5 -c 1" window lands
    // on fwd_kernel (validated last round).
    prep_kernel<<<(T + 96 + 255) / 256, 256>>>(rolls, T);
    dummy_kernel<<<1, 32>>>();
    dummy_kernel<<<1, 32>>>();

    fwd_kernel<<<1, 64>>>(rolls, trans, table, T);
    bp_chunk_kernel<<<nc, 512>>>(trans, T);
    compose_kernel<<<1, 256>>>(T);
    fill_kernel<<<nc, L>>>((float*)d_out, T, out_size);
}

// round 6
// speedup vs baseline: 1.5616x; 1.5616x over previous
#include <cuda_runtime.h>

#define S 64
#define MAXT 262144
#define L 512
#define NCMAX ((MAXT + L - 1) / L)

// ---- scratch (__device__ globals: no allocation allowed) ----
__device__ float g_e_buf[(size_t)MAXT * S];                    // e_t rows (+pad)
__device__ float g_ll[(size_t)(MAXT + 8) * S];                 // ll_t rows (+8 pad rows)
__device__ unsigned char g_walk[(size_t)NCMAX * S * L];        // per-chunk walks (16 MB)
__device__ int g_boundary[NCMAX + 2];
__device__ int g_final_state;
__device__ float g_final_score;

__device__ __forceinline__ float fmax3(float a, float b, float c) {
    return fmaxf(fmaxf(a, b), c);
}

// =====================================================================
// Kernel 0a: precompute full emission stream g_ll[t][j] = table[rolls[t]][j]
// (rows T..T+7 padded with the last row so the serial loop never clamps)
// =====================================================================
__global__ void prep_ll(const int* __restrict__ rolls,
                        const float* __restrict__ table, int T)
{
    int idx = blockIdx.x * blockDim.x + threadIdx.x;
    int t = idx >> 6, j = idx & 63;
    if (t < T + 8) {
        int tt = (t < T) ? t : (T - 1);
        g_ll[(size_t)t * S + j] = table[rolls[tt] * S + j];
    }
}

// Kernel 0b: no-op launch-index shims (keep ncu -s 5 landing on fwd_kernel)
__global__ void dummy_kernel() {}

// =====================================================================
// Kernel 1: serial Viterbi forward (values only). 128 threads, 4 warps.
// Thread pair per state j: half=0 covers i 0..31, half=1 covers 32..63.
// Emissions stream from g_ll via a 6-deep register ring (no dependent
// loads, no index math on the hot path).
// =====================================================================
__global__ __launch_bounds__(128, 1)
void fwd_kernel(const float* __restrict__ trans, int T)
{
    // padded e layout: i<32 at [i], i>=32 at [36+i-32] -> bank-disjoint halves
    __shared__ __align__(16) float smem_e[2][68];
    __shared__ float smem_d[S];

    const int tid = threadIdx.x;
    const int w = tid >> 5, l = tid & 31;
    const int j = w * 16 + (l >> 1);
    const int half = l & 1;
    const int ibase = half << 5;
    const bool lead = (half == 0);
    const int pos = (j < 32) ? j : (36 + (j - 32));
    const int ebOff = half ? 36 : 0;

    float TR[32];
#pragma unroll
    for (int k = 0; k < 32; k++) TR[k] = trans[j * 65 + ibase + k];

    // ---- init: delta_0 = trans[:,64] + ll_0 ; e_1 = ll_1 + delta_0 ----
    {
        float ll0 = g_ll[j];
        float d0 = trans[j * 65 + 64] + ll0;
        if (T == 1 && lead) smem_d[j] = d0;
        float e1 = g_ll[S + j] + d0;
        if (lead) smem_e[1][pos] = e1;
        else      g_e_buf[j] = e1;
    }
    // ring: rA..rF = ll[2..7]; step t consumes ll[t+1], loads ll[t+7]
    float rA = g_ll[2 * S + j];
    float rB = g_ll[3 * S + j];
    float rC = g_ll[4 * S + j];
    float rD = g_ll[5 * S + j];
    float rE = g_ll[6 * S + j];
    float rF = g_ll[7 * S + j];
    const float* llp = g_ll + 8 * S + j;            // ll[t+7] at t=1
    float* epp = g_e_buf + (size_t)S + j;           // e store for t=1
    __syncthreads();

    float delta = 0.0f;

    // One step: STATIC parity RP/WP, ring reg RCONS consumed, OFF = 0..5.
    // Candidates via FFMA-imm (E*1.0+TR bit-exact, rt=1); quad-major
    // FMNMX tree; shfl.bfly pair-combine.
#define VSTEP(RP, WP, RCONS, OFF)                                              \
    {                                                                          \
        float llNew = llp[(OFF) * S];                                          \
        float mq[8];                                                           \
        {                                                                      \
            const float4* eb =                                                 \
                reinterpret_cast<const float4*>(&smem_e[RP][ebOff]);           \
            _Pragma("unroll")                                                  \
            for (int q = 0; q < 8; q++) {                                      \
                float4 f = eb[q];                                              \
                float a = __fmaf_rn(f.x, 1.0f, TR[4*q]);                       \
                float b = __fmaf_rn(f.y, 1.0f, TR[4*q+1]);                     \
                float c = __fmaf_rn(f.z, 1.0f, TR[4*q+2]);                     \
                float d = __fmaf_rn(f.w, 1.0f, TR[4*q+3]);                     \
                mq[q] = fmaxf(fmaxf(a, b), fmaxf(c, d));                       \
            }                                                                  \
        }                                                                      \
        float c0 = fmax3(mq[0], mq[1], mq[2]);                                 \
        float c1 = fmax3(mq[3], mq[4], mq[5]);                                 \
        float c2 = fmaxf(mq[6], mq[7]);                                        \
        float m  = fmax3(c0, c1, c2);                                          \
        float mo = __shfl_xor_sync(0xffffffffu, m, 1);                         \
        delta = fmaxf(m, mo);                                                  \
        float ep = RCONS + delta;        /* e_{t+1} = ll_{t+1} + delta_t */    \
        if (lead) smem_e[WP][pos] = ep;                                        \
        else      epp[(OFF) * S] = ep;                                         \
        RCONS = llNew;                                                         \
        __syncthreads();                                                       \
    }

    int t = 1;
    // main loop: 6 steps per iter; parity at t odd: (1,0),(0,1) x3
    for (; t + 5 < T; t += 6) {
        VSTEP(1, 0, rA, 0);
        VSTEP(0, 1, rB, 1);
        VSTEP(1, 0, rC, 2);
        VSTEP(0, 1, rD, 3);
        VSTEP(1, 0, rE, 4);
        VSTEP(0, 1, rF, 5);
        llp += 6 * S;
        epp += 6 * S;
    }
#undef VSTEP

    // tail (<=5 steps): runtime parity, direct ll load (stall irrelevant)
    for (; t < T; t++) {
        const int rp = t & 1, wp = (t + 1) & 1;
        float mq[8];
        {
            const float4* eb = reinterpret_cast<const float4*>(&smem_e[rp][ebOff]);
#pragma unroll
            for (int q = 0; q < 8; q++) {
                float4 f = eb[q];
                float a = __fmaf_rn(f.x, 1.0f, TR[4*q]);
                float b = __fmaf_rn(f.y, 1.0f, TR[4*q+1]);
                float c = __fmaf_rn(f.z, 1.0f, TR[4*q+2]);
                float d = __fmaf_rn(f.w, 1.0f, TR[4*q+3]);
                mq[q] = fmaxf(fmaxf(a, b), fmaxf(c, d));
            }
        }
        float c0 = fmax3(mq[0], mq[1], mq[2]);
        float c1 = fmax3(mq[3], mq[4], mq[5]);
        float c2 = fmaxf(mq[6], mq[7]);
        float m  = fmax3(c0, c1, c2);
        float mo = __shfl_xor_sync(0xffffffffu, m, 1);
        delta = fmaxf(m, mo);
        float ep = g_ll[(size_t)(t + 1) * S + j] + delta;
        if (lead) smem_e[wp][pos] = ep;
        else      g_e_buf[(size_t)t * S + j] = ep;
        __syncthreads();
    }

    if (T > 1 && lead) smem_d[j] = delta;
    __syncthreads();
    if (tid == 0) {
        float best = smem_d[0]; int bi = 0;
        for (int q = 1; q < S; q++) {           // first-argmax (strict >)
            float vq = smem_d[q];
            if (vq > best) { best = vq; bi = q; }
        }
        g_final_state = bi;
        g_final_score = best;
    }
}

// =====================================================================
// Kernel 2: per-chunk backpointer recompute (bit-identical candidates,
// first-argmax via ascending strict >) + all-64-endstate backtrack walks.
// =====================================================================
__global__ __launch_bounds__(512, 1)
void bp_chunk_kernel(const float* __restrict__ trans, int T)
{
    __shared__ signed char bp_s[L * S];                 // 32 KB
    __shared__ __align__(16) float se[8][S];
    const int c = blockIdx.x;
    const int tid = threadIdx.x;
    const int tg = tid >> 6;
    const int j = tid & 63;
    int nr = (T - 1) - c * L; if (nr > L) nr = L; if (nr < 0) nr = 0;

    float TRv[64];
#pragma unroll
    for (int i = 0; i < 64; i++) TRv[i] = trans[j * 65 + i];

    for (int k = 0; k < L / 8; k++) {
        const int r = k * 8 + tg;
        const bool act = r < nr;
        if (act) se[tg][j] = g_e_buf[((size_t)(c * L + r)) * S + j];
        __syncthreads();
        if (act) {
            const float4* ep = reinterpret_cast<const float4*>(se[tg]);
            float4 e0 = ep[0];
            float m = TRv[0] + e0.x; int a = 0;
            float cc = TRv[1] + e0.y; if (cc > m) { m = cc; a = 1; }
            cc = TRv[2] + e0.z; if (cc > m) { m = cc; a = 2; }
            cc = TRv[3] + e0.w; if (cc > m) { m = cc; a = 3; }
#pragma unroll
            for (int q = 1; q < 16; q++) {
                float4 ev = ep[q];
                cc = TRv[4*q]   + ev.x; if (cc > m) { m = cc; a = 4*q;   }
                cc = TRv[4*q+1] + ev.y; if (cc > m) { m = cc; a = 4*q+1; }
                cc = TRv[4*q+2] + ev.z; if (cc > m) { m = cc; a = 4*q+2; }
                cc = TRv[4*q+3] + ev.w; if (cc > m) { m = cc; a = 4*q+3; }
            }
            bp_s[r * S + j] = (signed char)a;
        }
        __syncthreads();
    }

    if (tid < S) {
        int s = tid;
        const size_t wb = ((size_t)c * S + tid) * L;
        if (nr < L) g_walk[wb + nr] = (unsigned char)s;
        for (int r = nr - 1; r >= 0; r--) {
            s = bp_s[r * S + s];
            g_walk[wb + r] = (unsigned char)s;
        }
    }
}

// =====================================================================
// Kernel 3: serial chunk-map composition -> per-chunk boundary states
// =====================================================================
__global__ void compose_kernel(int T)
{
    __shared__ unsigned char mp[L * S];
    int nc = (T >= 2) ? ((T - 2) / L + 1) : 1;
    for (int q = threadIdx.x; q < nc * S; q += blockDim.x)
        mp[q] = g_walk[(size_t)q * L];
    __syncthreads();
    if (threadIdx.x == 0) {
        int s = g_final_state;
        g_boundary[nc] = s;
        for (int c = nc - 1; c >= 0; c--) {
            s = mp[c * S + s];
            g_boundary[c] = s;
        }
    }
}

// =====================================================================
// Kernel 4: parallel path fill, reverse-time order: out[T-1-t] = s_t
// =====================================================================
__global__ void fill_kernel(float* __restrict__ out, int T, int out_size)
{
    const int c = blockIdx.x;
    const int m = threadIdx.x;
    const int t = c * L + m;
    if (t < T) {
        const int sel = g_boundary[c + 1];
        unsigned char s = g_walk[((size_t)c * S + sel) * L + m];
        const int oi = T - 1 - t;
        if (oi >= 0 && oi < out_size) out[oi] = (float)s;
    }
    if (c == 0 && m == 0 && T < out_size) out[T] = g_final_score;
}

// =====================================================================
extern "C" void kernel_launch(void* const* d_in, const int* in_sizes, int n_in,
                              void* d_out, int out_size)
{
    const int* rolls = nullptr;
    const float* trans = nullptr;
    const float* table = nullptr;
    int T = 0;
    for (int i = 0; i < n_in; i++) {
        const int sz = in_sizes[i];
        if (sz == 64 * 65)       trans = (const float*)d_in[i];
        else if (sz == 128 * 64) table = (const float*)d_in[i];
        else { rolls = (const int*)d_in[i]; T = sz; }
    }
    if (!rolls || !trans || !table || T < 1) return;
    if (T > MAXT) T = MAXT;

    int nc = (T >= 2) ? ((T - 2) / L + 1) : 1;

    // 3 launches ahead of fwd so ncu's fixed "-s 5 -c 1" window lands on fwd.
    prep_ll<<<((T + 8) * S + 255) / 256, 256>>>(rolls, table, T);
    dummy_kernel<<<1, 32>>>();
    dummy_kernel<<<1, 32>>>();

    fwd_kernel<<<1, 128>>>(trans, T);
    bp_chunk_kernel<<<nc, 512>>>(trans, T);
    compose_kernel<<<1, 256>>>(T);
    fill_kernel<<<nc, L>>>((float*)d_out, T, out_size);
}